// round 15
// baseline (speedup 1.0000x reference)
#include <cuda_runtime.h>
#include <math_constants.h>

#define BATCH  64
#define NHEADS 32
#define HDIM   128
#define KVLEN  4096
#define EMBED  4096
#define NQKV   4352   // EMBED + 2*HDIM
#define LASTK  (KVLEN - 1)
#define SPLITK 4
#define KSEG   (EMBED / SPLITK)   // 1024
#define NSEG   8                  // kv segments for split-KV attention
#define SEGLEN (KVLEN / NSEG)     // 512
#define CHUNK  32                 // keys per pipelined chunk
#define NCH    (SEGLEN / CHUNK)   // 16

// ---------------- scratch (device addrs via cudaGetSymbolAddress only) ------
__device__ float g_qkv[BATCH * NQKV];
__device__ float g_pv[BATCH * NSEG * NHEADS * HDIM];
__device__ float g_ml[BATCH * NSEG * 64];               // m (0..31), l (32..63)
__device__ float g_attn[BATCH * EMBED];
__device__ float g_part[SPLITK * 64 * NQKV];

// ---------------- tf32 mma / cp.async helpers --------------------------------
__device__ __forceinline__ unsigned f2tf(float x) {
    unsigned r; asm("cvt.rna.tf32.f32 %0, %1;" : "=r"(r) : "f"(x)); return r;
}
__device__ __forceinline__ void split_tf(float x, float& hi, float& lo) {
    unsigned h = f2tf(x);
    hi = __uint_as_float(h);
    lo = __uint_as_float(f2tf(x - hi));
}
__device__ __forceinline__ void mma8(float* c,
    unsigned a0, unsigned a1, unsigned a2, unsigned a3, unsigned b0, unsigned b1)
{
    asm volatile(
        "mma.sync.aligned.m16n8k8.row.col.f32.tf32.tf32.f32 "
        "{%0,%1,%2,%3},{%4,%5,%6,%7},{%8,%9},{%0,%1,%2,%3};"
        : "+f"(c[0]), "+f"(c[1]), "+f"(c[2]), "+f"(c[3])
        : "r"(a0), "r"(a1), "r"(a2), "r"(a3), "r"(b0), "r"(b1));
}
__device__ __forceinline__ void cpa16(float* smem_dst, const float* gsrc) {
    unsigned s = (unsigned)__cvta_generic_to_shared(smem_dst);
    asm volatile("cp.async.cg.shared.global [%0], [%1], 16;" :: "r"(s), "l"(gsrc));
}

// =============================================================================
// Split-K compensated-tf32 GEMM: R9 structure (BM=64,BN=32,BK=32, double-buf)
// with hi/lo PRE-SPLIT at staging (the one perf change under test).
// Inner loop is pure LDS + mma: no cvt/sub contending with tensor issue.
// Smem: 55.3 KB static.
// =============================================================================
__global__ __launch_bounds__(256) void gemm_tf32_kernel(
    const float* __restrict__ Hm, const float* __restrict__ W,
    float* __restrict__ part, int N)
{
    __shared__ float Ah[2][64][36];
    __shared__ float Al[2][64][36];
    __shared__ float Bh[2][32][36];
    __shared__ float Bl[2][32][36];

    const int tid = threadIdx.x;
    const int n0 = blockIdx.x * 32;
    const int s  = blockIdx.y;
    const int kb0 = s * KSEG;

    const int lane = tid & 31, wid = tid >> 5;
    const int gid = lane >> 2, t4 = lane & 3;
    const int wm = (wid >> 1) * 16;
    const int wn = (wid & 1) * 16;

    const int am = tid >> 2, ak = (tid & 3) * 8;   // A: 2 float4/thread (8 elems)
    const int bk = tid >> 3, bn = (tid & 7) * 4;   // B: 1 float4/thread (4 elems)

    float acc[2][4];
#pragma unroll
    for (int j = 0; j < 2; ++j)
#pragma unroll
        for (int q = 0; q < 4; ++q) acc[j][q] = 0.f;

    float4 av0, av1, bv;
    auto commit = [&](int buf) {
        float h, l;
        split_tf(av0.x, h, l); Ah[buf][am][ak    ] = h; Al[buf][am][ak    ] = l;
        split_tf(av0.y, h, l); Ah[buf][am][ak + 1] = h; Al[buf][am][ak + 1] = l;
        split_tf(av0.z, h, l); Ah[buf][am][ak + 2] = h; Al[buf][am][ak + 2] = l;
        split_tf(av0.w, h, l); Ah[buf][am][ak + 3] = h; Al[buf][am][ak + 3] = l;
        split_tf(av1.x, h, l); Ah[buf][am][ak + 4] = h; Al[buf][am][ak + 4] = l;
        split_tf(av1.y, h, l); Ah[buf][am][ak + 5] = h; Al[buf][am][ak + 5] = l;
        split_tf(av1.z, h, l); Ah[buf][am][ak + 6] = h; Al[buf][am][ak + 6] = l;
        split_tf(av1.w, h, l); Ah[buf][am][ak + 7] = h; Al[buf][am][ak + 7] = l;
        split_tf(bv.x, h, l);  Bh[buf][bk][bn    ] = h; Bl[buf][bk][bn    ] = l;
        split_tf(bv.y, h, l);  Bh[buf][bk][bn + 1] = h; Bl[buf][bk][bn + 1] = l;
        split_tf(bv.z, h, l);  Bh[buf][bk][bn + 2] = h; Bl[buf][bk][bn + 2] = l;
        split_tf(bv.w, h, l);  Bh[buf][bk][bn + 3] = h; Bl[buf][bk][bn + 3] = l;
    };

    av0 = *(const float4*)(Hm + (size_t)am * EMBED + kb0 + ak);
    av1 = *(const float4*)(Hm + (size_t)am * EMBED + kb0 + ak + 4);
    bv  = *(const float4*)(W + (size_t)(kb0 + bk) * N + n0 + bn);
    commit(0);
    __syncthreads();

    const int NC = KSEG / 32;   // 32
    for (int c = 0; c < NC; ++c) {
        const int buf = c & 1;
        if (c + 1 < NC) {
            const int k0 = kb0 + (c + 1) * 32;
            av0 = *(const float4*)(Hm + (size_t)am * EMBED + k0 + ak);
            av1 = *(const float4*)(Hm + (size_t)am * EMBED + k0 + ak + 4);
            bv  = *(const float4*)(W + (size_t)(k0 + bk) * N + n0 + bn);
        }
#pragma unroll
        for (int k8 = 0; k8 < 4; ++k8) {
            const int kk = k8 * 8;
            const unsigned a0h = __float_as_uint(Ah[buf][wm + gid    ][kk + t4    ]);
            const unsigned a1h = __float_as_uint(Ah[buf][wm + gid + 8][kk + t4    ]);
            const unsigned a2h = __float_as_uint(Ah[buf][wm + gid    ][kk + t4 + 4]);
            const unsigned a3h = __float_as_uint(Ah[buf][wm + gid + 8][kk + t4 + 4]);
            const unsigned a0l = __float_as_uint(Al[buf][wm + gid    ][kk + t4    ]);
            const unsigned a1l = __float_as_uint(Al[buf][wm + gid + 8][kk + t4    ]);
            const unsigned a2l = __float_as_uint(Al[buf][wm + gid    ][kk + t4 + 4]);
            const unsigned a3l = __float_as_uint(Al[buf][wm + gid + 8][kk + t4 + 4]);
#pragma unroll
            for (int j = 0; j < 2; ++j) {
                const int col = wn + 8 * j + gid;
                const unsigned b0h = __float_as_uint(Bh[buf][kk + t4    ][col]);
                const unsigned b1h = __float_as_uint(Bh[buf][kk + t4 + 4][col]);
                const unsigned b0l = __float_as_uint(Bl[buf][kk + t4    ][col]);
                const unsigned b1l = __float_as_uint(Bl[buf][kk + t4 + 4][col]);
                mma8(acc[j], a0h, a1h, a2h, a3h, b0h, b1h);
                mma8(acc[j], a0h, a1h, a2h, a3h, b0l, b1l);
                mma8(acc[j], a0l, a1l, a2l, a3l, b0h, b1h);
            }
        }
        if (c + 1 < NC) {
            commit(buf ^ 1);
            __syncthreads();
        }
    }

    const int r0 = wm + gid, r1 = wm + gid + 8;
#pragma unroll
    for (int j = 0; j < 2; ++j) {
        const int col = n0 + wn + 8 * j + 2 * t4;
        *(float2*)(part + ((size_t)(s * 64 + r0)) * N + col) = make_float2(acc[j][0], acc[j][1]);
        *(float2*)(part + ((size_t)(s * 64 + r1)) * N + col) = make_float2(acc[j][2], acc[j][3]);
    }
}

__global__ __launch_bounds__(256) void reduce_gemm_kernel(
    const float* __restrict__ part, const float* __restrict__ bias,
    float* __restrict__ outp, int N)
{
    const int o = blockIdx.x * 256 + threadIdx.x;
    const int n = o % N;
    float v = bias[n];
#pragma unroll
    for (int s = 0; s < SPLITK; ++s) v += part[(size_t)s * 64 * N + o];
    outp[o] = v;
}

// Tiny no-op: shifts fattn to launch #4 so the ncu `-c 1` capture (which
// empirically lands on launch #4) profiles fattn next round. ~1 us cost.
__global__ void dummy_kernel() {}

// =============================================================================
// FUSED flash-decode attention (unchanged from R13: NSEG=8, 32-key chunks,
// 3-deep cp.async ring — measured equal to depth 2, kept).
// =============================================================================
#define SM_KS 0
#define SM_VS 12288
#define SM_SC 24960
#define SM_M  26112
#define SM_L  26144
#define SM_F  26176
#define FATTN_SMEM_BYTES (26208 * 4)

__global__ __launch_bounds__(256, 2) void fattn_kernel(
    const float* __restrict__ past, float* __restrict__ out_past)
{
    extern __shared__ float sm[];
    float* Ks = sm + SM_KS;     // [buf][key][128], col ^ ((key&7)<<2)
    float* Vs = sm + SM_VS;     // [buf][key][132]
    float* Sc = sm + SM_SC;     // [head][36]
    float* s_m = sm + SM_M; float* s_l = sm + SM_L; float* s_f = sm + SM_F;

    const int seg = blockIdx.x, b = blockIdx.y;
    const int tid = threadIdx.x;
    const int lane = tid & 31, wid = tid >> 5;
    const int gid = lane >> 2, t4 = lane & 3;
    const int wm  = (wid >> 2) * 16;     // head group 0/16
    const int qwn = (wid & 3) * 8;       // QK: 8-key strip
    const int pwn = (wid & 3) * 32;      // PV: 32-dim strip
    const float* qkvb = g_qkv + (size_t)b * NQKV;

    if (tid < 32) { s_m[tid] = -CUDART_INF_F; s_l[tid] = 0.f; }

    // ---- hoist Q fragments (tf32 once) ----
    unsigned qa[16][4];
    {
        const float* q0 = qkvb + (wm + gid) * HDIM;
        const float* q1 = qkvb + (wm + gid + 8) * HDIM;
#pragma unroll
        for (int ks8 = 0; ks8 < 16; ++ks8) {
            const int kk = 8 * ks8;
            qa[ks8][0] = f2tf(__ldg(q0 + kk + t4));
            qa[ks8][1] = f2tf(__ldg(q1 + kk + t4));
            qa[ks8][2] = f2tf(__ldg(q0 + kk + t4 + 4));
            qa[ks8][3] = f2tf(__ldg(q1 + kk + t4 + 4));
        }
    }

    float pacc[4][4];
#pragma unroll
    for (int j = 0; j < 4; ++j)
#pragma unroll
        for (int q = 0; q < 4; ++q) pacc[j][q] = 0.f;

    const float scale = 0.08838834764831845f;   // 1/sqrt(128)

    auto stage = [&](int c, int sbuf) {
        const int kbase = seg * SEGLEN + c * CHUNK;
#pragma unroll
        for (int i = 0; i < 4; ++i) {
            const int u = tid + 256 * i;       // 0..1023
            const int key = u >> 5, du = u & 31;
            const int gk = kbase + key;
            const float *srcK, *srcV;
            if (gk == LASTK) {
                srcK = qkvb + EMBED + 4 * du;
                srcV = qkvb + EMBED + HDIM + 4 * du;
            } else {
                const float* s = past + ((size_t)b * KVLEN + gk) * 256;
                srcK = s + 4 * du;
                srcV = s + HDIM + 4 * du;
            }
            cpa16(Ks + sbuf * 4096 + key * 128 + ((4 * du) ^ ((key & 7) << 2)), srcK);
            cpa16(Vs + sbuf * 4224 + key * 132 + 4 * du, srcV);
        }
        asm volatile("cp.async.commit_group;" ::: "memory");
    };

    stage(0, 0);
    stage(1, 1);

    for (int c = 0; c < NCH; ++c) {
        const int buf = c % 3;
        if (c + 2 < NCH) {
            stage(c + 2, (c + 2) % 3);                              // issue first
            asm volatile("cp.async.wait_group 2;" ::: "memory");    // chunk c done
        } else if (c + 1 < NCH) {
            asm volatile("cp.async.wait_group 1;" ::: "memory");
        } else {
            asm volatile("cp.async.wait_group 0;" ::: "memory");
        }
        __syncthreads();

        const float* KsB = Ks + buf * 4096;
        const float* VsB = Vs + buf * 4224;

        // ---- out_past copy from smem ----
        {
            const int kbase = seg * SEGLEN + c * CHUNK;
#pragma unroll
            for (int i = 0; i < 4; ++i) {
                const int u = tid + 256 * i;
                const int key = u >> 5, du = u & 31;
                const float4 kv = *(const float4*)(KsB + key * 128 + ((4 * du) ^ ((key & 7) << 2)));
                const float4 vv = *(const float4*)(VsB + key * 132 + 4 * du);
                float* dst = out_past + ((size_t)b * KVLEN + kbase + key) * 256;
                *(float4*)(dst + 4 * du) = kv;
                *(float4*)(dst + HDIM + 4 * du) = vv;
            }
        }

        // ---- QK mma: 32 heads x 8 keys per warp (m16n8), K=128 ----
        float qacc[4] = {0.f, 0.f, 0.f, 0.f};
        {
            const int krow = qwn + gid;
            const float* Kr = KsB + krow * 128;
            const int ksw = (krow & 7) << 2;
#pragma unroll
            for (int ks8 = 0; ks8 < 16; ++ks8) {
                const int kk = 8 * ks8;
                const unsigned b0 = f2tf(Kr[(kk + t4)     ^ ksw]);
                const unsigned b1 = f2tf(Kr[(kk + t4 + 4) ^ ksw]);
                mma8(qacc, qa[ks8][0], qa[ks8][1], qa[ks8][2], qa[ks8][3], b0, b1);
            }
            const int h0 = wm + gid, h1 = wm + gid + 8;
            const int col = qwn + 2 * t4;
            Sc[h0 * 36 + col]     = qacc[0] * scale;
            Sc[h0 * 36 + col + 1] = qacc[1] * scale;
            Sc[h1 * 36 + col]     = qacc[2] * scale;
            Sc[h1 * 36 + col + 1] = qacc[3] * scale;
        }
        __syncthreads();

        // ---- online softmax: 8 threads/head-row, 4 keys each ----
        {
            const int row = tid >> 3, k0 = (tid & 7) * 4;
            float v4[4];
            float lm = -CUDART_INF_F;
#pragma unroll
            for (int q = 0; q < 4; ++q) { v4[q] = Sc[row * 36 + k0 + q]; lm = fmaxf(lm, v4[q]); }
#pragma unroll
            for (int o = 4; o; o >>= 1) lm = fmaxf(lm, __shfl_xor_sync(0xffffffffu, lm, o));
            const float old_m = s_m[row];
            const float nm = fmaxf(old_m, lm);
            float sum = 0.f;
#pragma unroll
            for (int q = 0; q < 4; ++q) {
                const float e = __expf(v4[q] - nm);
                Sc[row * 36 + k0 + q] = e;
                sum += e;
            }
#pragma unroll
            for (int o = 4; o; o >>= 1) sum += __shfl_xor_sync(0xffffffffu, sum, o);
            if ((tid & 7) == 0) {
                const float f = __expf(old_m - nm);
                s_f[row] = f;
                s_l[row] = s_l[row] * f + sum;
                s_m[row] = nm;
            }
        }
        __syncthreads();

        // ---- rescale + PV mma: 32 heads x 32 dims per warp, K=32 ----
        {
            const float f0 = s_f[wm + gid], f1 = s_f[wm + gid + 8];
#pragma unroll
            for (int j = 0; j < 4; ++j) {
                pacc[j][0] *= f0; pacc[j][1] *= f0;
                pacc[j][2] *= f1; pacc[j][3] *= f1;
            }
        }
#pragma unroll
        for (int k8 = 0; k8 < 4; ++k8) {
            const int kk = 8 * k8;
            const unsigned a0 = f2tf(Sc[(wm + gid)     * 36 + kk + t4    ]);
            const unsigned a1 = f2tf(Sc[(wm + gid + 8) * 36 + kk + t4    ]);
            const unsigned a2 = f2tf(Sc[(wm + gid)     * 36 + kk + t4 + 4]);
            const unsigned a3 = f2tf(Sc[(wm + gid + 8) * 36 + kk + t4 + 4]);
#pragma unroll
            for (int j = 0; j < 4; ++j) {
                const unsigned b0 = f2tf(VsB[(kk + t4)     * 132 + pwn + 8 * j + gid]);
                const unsigned b1 = f2tf(VsB[(kk + t4 + 4) * 132 + pwn + 8 * j + gid]);
                mma8(pacc[j], a0, a1, a2, a3, b0, b1);
            }
        }
        __syncthreads();   // buf free before stage(c+3) next iteration
    }

    // ---- emit partial + (m, l) ----
    float* pp = g_pv + (size_t)(b * NSEG + seg) * NHEADS * HDIM;
    const int h0 = wm + gid, h1 = wm + gid + 8;
#pragma unroll
    for (int j = 0; j < 4; ++j) {
        const int d = pwn + 8 * j + 2 * t4;
        *(float2*)(pp + h0 * HDIM + d) = make_float2(pacc[j][0], pacc[j][1]);
        *(float2*)(pp + h1 * HDIM + d) = make_float2(pacc[j][2], pacc[j][3]);
    }
    if (tid < 32) {
        g_ml[(size_t)(b * NSEG + seg) * 64 + tid]      = s_m[tid];
        g_ml[(size_t)(b * NSEG + seg) * 64 + 32 + tid] = s_l[tid];
    }
}

// =============================================================================
// Combine: log-sum-exp merge of NSEG partials -> g_attn[b][h][d].
// =============================================================================
__global__ __launch_bounds__(512) void combine_kernel()
{
    const int o = blockIdx.x * 512 + threadIdx.x;   // 262144
    const int bh = o >> 7, d = o & 127;
    const int b = bh >> 5, h = bh & 31;

    float M = -CUDART_INF_F;
    float ms[NSEG];
#pragma unroll
    for (int s = 0; s < NSEG; ++s) {
        ms[s] = g_ml[(size_t)(b * NSEG + s) * 64 + h];
        M = fmaxf(M, ms[s]);
    }
    float L = 0.f, acc = 0.f;
#pragma unroll
    for (int s = 0; s < NSEG; ++s) {
        const float w = __expf(ms[s] - M);
        L   += w * g_ml[(size_t)(b * NSEG + s) * 64 + 32 + h];
        acc += w * g_pv[((size_t)(b * NSEG + s) * NHEADS + h) * HDIM + d];
    }
    g_attn[(size_t)b * EMBED + h * HDIM + d] = acc / L;
}

// =============================================================================
// Input resolution BY ELEMENT COUNT.
// =============================================================================
extern "C" void kernel_launch(void* const* d_in, const int* in_sizes, int n_in,
                              void* d_out, int out_size)
{
    (void)out_size;
    const float* hidden = nullptr;
    const float* past   = nullptr;
    const float* caw = nullptr; const float* cab = nullptr;
    const float* cpw = nullptr; const float* cpb = nullptr;

    for (int i = 0; i < n_in; ++i) {
        const long long sz = in_sizes[i];
        const void* p = d_in[i];
        switch (sz) {
            case 67108864LL: past = (const float*)p; break;
            case 17825792LL: caw  = (const float*)p; break;
            case 16777216LL: cpw  = (const float*)p; break;
            case 4352LL:     cab  = (const float*)p; break;
            case 4096LL:     cpb  = (const float*)p; break;
            case 262144LL:
                if (!hidden) hidden = (const float*)p;   // 1st = hidden, 2nd = mask
                break;
            default: break;
        }
    }

    void* p_qkv = nullptr; void* p_attn = nullptr; void* p_part = nullptr;
    cudaGetSymbolAddress(&p_qkv,  g_qkv);
    cudaGetSymbolAddress(&p_attn, g_attn);
    cudaGetSymbolAddress(&p_part, g_part);

    cudaFuncSetAttribute(fattn_kernel,
                         cudaFuncAttributeMaxDynamicSharedMemorySize,
                         FATTN_SMEM_BYTES);

    float* out      = (float*)d_out;                    // output 0: [64, 4096]
    float* out_past = out + (size_t)BATCH * EMBED;      // output 1: [64, 4096, 256]

    gemm_tf32_kernel<<<dim3(NQKV / 32, SPLITK), 256>>>(hidden, caw, (float*)p_part, NQKV);   // #1
    reduce_gemm_kernel<<<64 * NQKV / 256, 256>>>((const float*)p_part, cab, (float*)p_qkv, NQKV); // #2
    dummy_kernel<<<1, 32>>>();                                                               // #3 (capture shim)
    fattn_kernel<<<dim3(NSEG, BATCH), 256, FATTN_SMEM_BYTES>>>(past, out_past);              // #4 <- profiled
    combine_kernel<<<512, 512>>>();                                                          // #5
    gemm_tf32_kernel<<<dim3(EMBED / 32, SPLITK), 256>>>((const float*)p_attn, cpw, (float*)p_part, EMBED); // #6
    reduce_gemm_kernel<<<64 * EMBED / 256, 256>>>((const float*)p_part, cpb, out, EMBED);    // #7
}

// round 16
// speedup vs baseline: 1.4920x; 1.4920x over previous
#include <cuda_runtime.h>
#include <math_constants.h>

#define BATCH  64
#define NHEADS 32
#define HDIM   128
#define KVLEN  4096
#define EMBED  4096
#define NQKV   4352   // EMBED + 2*HDIM
#define LASTK  (KVLEN - 1)
#define SPLITK 4
#define KSEG   (EMBED / SPLITK)   // 1024
#define NSEG   8                  // kv segments for split-KV attention
#define SEGLEN (KVLEN / NSEG)     // 512
#define CHUNK  32                 // keys per pipelined chunk
#define NCH    (SEGLEN / CHUNK)   // 16

// ---------------- scratch (device addrs via cudaGetSymbolAddress only) ------
__device__ float g_qkv[BATCH * NQKV];
__device__ float g_pv[BATCH * NSEG * NHEADS * HDIM];
__device__ float g_ml[BATCH * NSEG * 64];               // m (0..31), l (32..63)
__device__ float g_attn[BATCH * EMBED];
__device__ float g_part[SPLITK * 64 * NQKV];

// ---------------- tf32 mma / cp.async helpers --------------------------------
__device__ __forceinline__ unsigned f2tf(float x) {
    unsigned r; asm("cvt.rna.tf32.f32 %0, %1;" : "=r"(r) : "f"(x)); return r;
}
__device__ __forceinline__ void split_tf(float x, unsigned& hi, unsigned& lo) {
    hi = f2tf(x);
    lo = f2tf(x - __uint_as_float(hi));
}
__device__ __forceinline__ void mma8(float* c,
    unsigned a0, unsigned a1, unsigned a2, unsigned a3, unsigned b0, unsigned b1)
{
    asm volatile(
        "mma.sync.aligned.m16n8k8.row.col.f32.tf32.tf32.f32 "
        "{%0,%1,%2,%3},{%4,%5,%6,%7},{%8,%9},{%0,%1,%2,%3};"
        : "+f"(c[0]), "+f"(c[1]), "+f"(c[2]), "+f"(c[3])
        : "r"(a0), "r"(a1), "r"(a2), "r"(a3), "r"(b0), "r"(b1));
}
__device__ __forceinline__ void mma8x3(float* c,
    unsigned a0h, unsigned a1h, unsigned a2h, unsigned a3h,
    unsigned a0l, unsigned a1l, unsigned a2l, unsigned a3l,
    unsigned b0h, unsigned b1h, unsigned b0l, unsigned b1l)
{
    mma8(c, a0h, a1h, a2h, a3h, b0h, b1h);
    mma8(c, a0h, a1h, a2h, a3h, b0l, b1l);
    mma8(c, a0l, a1l, a2l, a3l, b0h, b1h);
}
__device__ __forceinline__ void cpa16(float* smem_dst, const float* gsrc) {
    unsigned s = (unsigned)__cvta_generic_to_shared(smem_dst);
    asm volatile("cp.async.cg.shared.global [%0], [%1], 16;" :: "r"(s), "l"(gsrc));
}

// =============================================================================
// Split-K tf32 GEMM, R9-proven skeleton (BM=64,BN=32,BK=32, inline splits).
// PASSES=3: compensated hi/lo (error-free vs fp32 inputs).
// PASSES=1: plain tf32 (1 cvt per operand, 1/3 the mma) — used for c_proj,
//           where the error budget allows it (measured RMS algebra).
// =============================================================================
template <int PASSES>
__global__ __launch_bounds__(256) void gemm_tf32_kernel(
    const float* __restrict__ Hm, const float* __restrict__ W,
    float* __restrict__ part, int N)
{
    __shared__ float As[2][64][36];
    __shared__ float Bs[2][32][36];

    const int tid = threadIdx.x;
    const int n0 = blockIdx.x * 32;
    const int s  = blockIdx.y;
    const int kb0 = s * KSEG;

    const int lane = tid & 31, wid = tid >> 5;
    const int gid = lane >> 2, t4 = lane & 3;
    const int wm = (wid >> 1) * 16;
    const int wn = (wid & 1) * 16;

    const int am = tid >> 2, ak = (tid & 3) * 8;
    const int bk = tid >> 3, bn = (tid & 7) * 4;

    float acc[2][4];
#pragma unroll
    for (int j = 0; j < 2; ++j)
#pragma unroll
        for (int q = 0; q < 4; ++q) acc[j][q] = 0.f;

    float4 av0, av1, bv;
    av0 = *(const float4*)(Hm + (size_t)am * EMBED + kb0 + ak);
    av1 = *(const float4*)(Hm + (size_t)am * EMBED + kb0 + ak + 4);
    bv  = *(const float4*)(W + (size_t)(kb0 + bk) * N + n0 + bn);
    *(float4*)&As[0][am][ak]     = av0;
    *(float4*)&As[0][am][ak + 4] = av1;
    *(float4*)&Bs[0][bk][bn]     = bv;
    __syncthreads();

    const int NC = KSEG / 32;
    for (int c = 0; c < NC; ++c) {
        const int buf = c & 1;
        if (c + 1 < NC) {
            const int k0 = kb0 + (c + 1) * 32;
            av0 = *(const float4*)(Hm + (size_t)am * EMBED + k0 + ak);
            av1 = *(const float4*)(Hm + (size_t)am * EMBED + k0 + ak + 4);
            bv  = *(const float4*)(W + (size_t)(k0 + bk) * N + n0 + bn);
        }
#pragma unroll
        for (int k8 = 0; k8 < 4; ++k8) {
            const int kk = k8 * 8;
            if (PASSES == 3) {
                unsigned a0h, a0l, a1h, a1l, a2h, a2l, a3h, a3l;
                split_tf(As[buf][wm + gid    ][kk + t4    ], a0h, a0l);
                split_tf(As[buf][wm + gid + 8][kk + t4    ], a1h, a1l);
                split_tf(As[buf][wm + gid    ][kk + t4 + 4], a2h, a2l);
                split_tf(As[buf][wm + gid + 8][kk + t4 + 4], a3h, a3l);
#pragma unroll
                for (int j = 0; j < 2; ++j) {
                    unsigned b0h, b0l, b1h, b1l;
                    split_tf(Bs[buf][kk + t4    ][wn + 8 * j + gid], b0h, b0l);
                    split_tf(Bs[buf][kk + t4 + 4][wn + 8 * j + gid], b1h, b1l);
                    mma8x3(acc[j], a0h, a1h, a2h, a3h, a0l, a1l, a2l, a3l,
                           b0h, b1h, b0l, b1l);
                }
            } else {
                const unsigned a0 = f2tf(As[buf][wm + gid    ][kk + t4    ]);
                const unsigned a1 = f2tf(As[buf][wm + gid + 8][kk + t4    ]);
                const unsigned a2 = f2tf(As[buf][wm + gid    ][kk + t4 + 4]);
                const unsigned a3 = f2tf(As[buf][wm + gid + 8][kk + t4 + 4]);
#pragma unroll
                for (int j = 0; j < 2; ++j) {
                    const unsigned b0 = f2tf(Bs[buf][kk + t4    ][wn + 8 * j + gid]);
                    const unsigned b1 = f2tf(Bs[buf][kk + t4 + 4][wn + 8 * j + gid]);
                    mma8(acc[j], a0, a1, a2, a3, b0, b1);
                }
            }
        }
        if (c + 1 < NC) {
            *(float4*)&As[buf ^ 1][am][ak]     = av0;
            *(float4*)&As[buf ^ 1][am][ak + 4] = av1;
            *(float4*)&Bs[buf ^ 1][bk][bn]     = bv;
            __syncthreads();
        }
    }

    const int r0 = wm + gid, r1 = wm + gid + 8;
#pragma unroll
    for (int j = 0; j < 2; ++j) {
        const int col = n0 + wn + 8 * j + 2 * t4;
        *(float2*)(part + ((size_t)(s * 64 + r0)) * N + col) = make_float2(acc[j][0], acc[j][1]);
        *(float2*)(part + ((size_t)(s * 64 + r1)) * N + col) = make_float2(acc[j][2], acc[j][3]);
    }
}

__global__ __launch_bounds__(256) void reduce_gemm_kernel(
    const float* __restrict__ part, const float* __restrict__ bias,
    float* __restrict__ outp, int N)
{
    const int o = blockIdx.x * 256 + threadIdx.x;
    const int n = o % N;
    float v = bias[n];
#pragma unroll
    for (int s = 0; s < SPLITK; ++s) v += part[(size_t)s * 64 * N + o];
    outp[o] = v;
}

// Tiny no-op: keeps fattn at launch #4 so the ncu `-c 1` capture profiles it.
__global__ void dummy_kernel() {}

// =============================================================================
// FUSED flash-decode attention (unchanged from R13's 254.5us passing run).
// =============================================================================
#define SM_KS 0
#define SM_VS 12288
#define SM_SC 24960
#define SM_M  26112
#define SM_L  26144
#define SM_F  26176
#define FATTN_SMEM_BYTES (26208 * 4)

__global__ __launch_bounds__(256, 2) void fattn_kernel(
    const float* __restrict__ past, float* __restrict__ out_past)
{
    extern __shared__ float sm[];
    float* Ks = sm + SM_KS;     // [buf][key][128], col ^ ((key&7)<<2)
    float* Vs = sm + SM_VS;     // [buf][key][132]
    float* Sc = sm + SM_SC;     // [head][36]
    float* s_m = sm + SM_M; float* s_l = sm + SM_L; float* s_f = sm + SM_F;

    const int seg = blockIdx.x, b = blockIdx.y;
    const int tid = threadIdx.x;
    const int lane = tid & 31, wid = tid >> 5;
    const int gid = lane >> 2, t4 = lane & 3;
    const int wm  = (wid >> 2) * 16;     // head group 0/16
    const int qwn = (wid & 3) * 8;       // QK: 8-key strip
    const int pwn = (wid & 3) * 32;      // PV: 32-dim strip
    const float* qkvb = g_qkv + (size_t)b * NQKV;

    if (tid < 32) { s_m[tid] = -CUDART_INF_F; s_l[tid] = 0.f; }

    // ---- hoist Q fragments (tf32 once) ----
    unsigned qa[16][4];
    {
        const float* q0 = qkvb + (wm + gid) * HDIM;
        const float* q1 = qkvb + (wm + gid + 8) * HDIM;
#pragma unroll
        for (int ks8 = 0; ks8 < 16; ++ks8) {
            const int kk = 8 * ks8;
            qa[ks8][0] = f2tf(__ldg(q0 + kk + t4));
            qa[ks8][1] = f2tf(__ldg(q1 + kk + t4));
            qa[ks8][2] = f2tf(__ldg(q0 + kk + t4 + 4));
            qa[ks8][3] = f2tf(__ldg(q1 + kk + t4 + 4));
        }
    }

    float pacc[4][4];
#pragma unroll
    for (int j = 0; j < 4; ++j)
#pragma unroll
        for (int q = 0; q < 4; ++q) pacc[j][q] = 0.f;

    const float scale = 0.08838834764831845f;   // 1/sqrt(128)

    auto stage = [&](int c, int sbuf) {
        const int kbase = seg * SEGLEN + c * CHUNK;
#pragma unroll
        for (int i = 0; i < 4; ++i) {
            const int u = tid + 256 * i;       // 0..1023
            const int key = u >> 5, du = u & 31;
            const int gk = kbase + key;
            const float *srcK, *srcV;
            if (gk == LASTK) {
                srcK = qkvb + EMBED + 4 * du;
                srcV = qkvb + EMBED + HDIM + 4 * du;
            } else {
                const float* s = past + ((size_t)b * KVLEN + gk) * 256;
                srcK = s + 4 * du;
                srcV = s + HDIM + 4 * du;
            }
            cpa16(Ks + sbuf * 4096 + key * 128 + ((4 * du) ^ ((key & 7) << 2)), srcK);
            cpa16(Vs + sbuf * 4224 + key * 132 + 4 * du, srcV);
        }
        asm volatile("cp.async.commit_group;" ::: "memory");
    };

    stage(0, 0);
    stage(1, 1);

    for (int c = 0; c < NCH; ++c) {
        const int buf = c % 3;
        if (c + 2 < NCH) {
            stage(c + 2, (c + 2) % 3);                              // issue first
            asm volatile("cp.async.wait_group 2;" ::: "memory");    // chunk c done
        } else if (c + 1 < NCH) {
            asm volatile("cp.async.wait_group 1;" ::: "memory");
        } else {
            asm volatile("cp.async.wait_group 0;" ::: "memory");
        }
        __syncthreads();

        const float* KsB = Ks + buf * 4096;
        const float* VsB = Vs + buf * 4224;

        // ---- out_past copy from smem ----
        {
            const int kbase = seg * SEGLEN + c * CHUNK;
#pragma unroll
            for (int i = 0; i < 4; ++i) {
                const int u = tid + 256 * i;
                const int key = u >> 5, du = u & 31;
                const float4 kv = *(const float4*)(KsB + key * 128 + ((4 * du) ^ ((key & 7) << 2)));
                const float4 vv = *(const float4*)(VsB + key * 132 + 4 * du);
                float* dst = out_past + ((size_t)b * KVLEN + kbase + key) * 256;
                *(float4*)(dst + 4 * du) = kv;
                *(float4*)(dst + HDIM + 4 * du) = vv;
            }
        }

        // ---- QK mma: 32 heads x 8 keys per warp (m16n8), K=128 ----
        float qacc[4] = {0.f, 0.f, 0.f, 0.f};
        {
            const int krow = qwn + gid;
            const float* Kr = KsB + krow * 128;
            const int ksw = (krow & 7) << 2;
#pragma unroll
            for (int ks8 = 0; ks8 < 16; ++ks8) {
                const int kk = 8 * ks8;
                const unsigned b0 = f2tf(Kr[(kk + t4)     ^ ksw]);
                const unsigned b1 = f2tf(Kr[(kk + t4 + 4) ^ ksw]);
                mma8(qacc, qa[ks8][0], qa[ks8][1], qa[ks8][2], qa[ks8][3], b0, b1);
            }
            const int h0 = wm + gid, h1 = wm + gid + 8;
            const int col = qwn + 2 * t4;
            Sc[h0 * 36 + col]     = qacc[0] * scale;
            Sc[h0 * 36 + col + 1] = qacc[1] * scale;
            Sc[h1 * 36 + col]     = qacc[2] * scale;
            Sc[h1 * 36 + col + 1] = qacc[3] * scale;
        }
        __syncthreads();

        // ---- online softmax: 8 threads/head-row, 4 keys each ----
        {
            const int row = tid >> 3, k0 = (tid & 7) * 4;
            float v4[4];
            float lm = -CUDART_INF_F;
#pragma unroll
            for (int q = 0; q < 4; ++q) { v4[q] = Sc[row * 36 + k0 + q]; lm = fmaxf(lm, v4[q]); }
#pragma unroll
            for (int o = 4; o; o >>= 1) lm = fmaxf(lm, __shfl_xor_sync(0xffffffffu, lm, o));
            const float old_m = s_m[row];
            const float nm = fmaxf(old_m, lm);
            float sum = 0.f;
#pragma unroll
            for (int q = 0; q < 4; ++q) {
                const float e = __expf(v4[q] - nm);
                Sc[row * 36 + k0 + q] = e;
                sum += e;
            }
#pragma unroll
            for (int o = 4; o; o >>= 1) sum += __shfl_xor_sync(0xffffffffu, sum, o);
            if ((tid & 7) == 0) {
                const float f = __expf(old_m - nm);
                s_f[row] = f;
                s_l[row] = s_l[row] * f + sum;
                s_m[row] = nm;
            }
        }
        __syncthreads();

        // ---- rescale + PV mma: 32 heads x 32 dims per warp, K=32 ----
        {
            const float f0 = s_f[wm + gid], f1 = s_f[wm + gid + 8];
#pragma unroll
            for (int j = 0; j < 4; ++j) {
                pacc[j][0] *= f0; pacc[j][1] *= f0;
                pacc[j][2] *= f1; pacc[j][3] *= f1;
            }
        }
#pragma unroll
        for (int k8 = 0; k8 < 4; ++k8) {
            const int kk = 8 * k8;
            const unsigned a0 = f2tf(Sc[(wm + gid)     * 36 + kk + t4    ]);
            const unsigned a1 = f2tf(Sc[(wm + gid + 8) * 36 + kk + t4    ]);
            const unsigned a2 = f2tf(Sc[(wm + gid)     * 36 + kk + t4 + 4]);
            const unsigned a3 = f2tf(Sc[(wm + gid + 8) * 36 + kk + t4 + 4]);
#pragma unroll
            for (int j = 0; j < 4; ++j) {
                const unsigned b0 = f2tf(VsB[(kk + t4)     * 132 + pwn + 8 * j + gid]);
                const unsigned b1 = f2tf(VsB[(kk + t4 + 4) * 132 + pwn + 8 * j + gid]);
                mma8(pacc[j], a0, a1, a2, a3, b0, b1);
            }
        }
        __syncthreads();   // buf free before stage(c+3) next iteration
    }

    // ---- emit partial + (m, l) ----
    float* pp = g_pv + (size_t)(b * NSEG + seg) * NHEADS * HDIM;
    const int h0 = wm + gid, h1 = wm + gid + 8;
#pragma unroll
    for (int j = 0; j < 4; ++j) {
        const int d = pwn + 8 * j + 2 * t4;
        *(float2*)(pp + h0 * HDIM + d) = make_float2(pacc[j][0], pacc[j][1]);
        *(float2*)(pp + h1 * HDIM + d) = make_float2(pacc[j][2], pacc[j][3]);
    }
    if (tid < 32) {
        g_ml[(size_t)(b * NSEG + seg) * 64 + tid]      = s_m[tid];
        g_ml[(size_t)(b * NSEG + seg) * 64 + 32 + tid] = s_l[tid];
    }
}

// =============================================================================
// Combine: log-sum-exp merge of NSEG partials -> g_attn[b][h][d].
// =============================================================================
__global__ __launch_bounds__(512) void combine_kernel()
{
    const int o = blockIdx.x * 512 + threadIdx.x;   // 262144
    const int bh = o >> 7, d = o & 127;
    const int b = bh >> 5, h = bh & 31;

    float M = -CUDART_INF_F;
    float ms[NSEG];
#pragma unroll
    for (int s = 0; s < NSEG; ++s) {
        ms[s] = g_ml[(size_t)(b * NSEG + s) * 64 + h];
        M = fmaxf(M, ms[s]);
    }
    float L = 0.f, acc = 0.f;
#pragma unroll
    for (int s = 0; s < NSEG; ++s) {
        const float w = __expf(ms[s] - M);
        L   += w * g_ml[(size_t)(b * NSEG + s) * 64 + 32 + h];
        acc += w * g_pv[((size_t)(b * NSEG + s) * NHEADS + h) * HDIM + d];
    }
    g_attn[(size_t)b * EMBED + h * HDIM + d] = acc / L;
}

// =============================================================================
// Input resolution BY ELEMENT COUNT.
// =============================================================================
extern "C" void kernel_launch(void* const* d_in, const int* in_sizes, int n_in,
                              void* d_out, int out_size)
{
    (void)out_size;
    const float* hidden = nullptr;
    const float* past   = nullptr;
    const float* caw = nullptr; const float* cab = nullptr;
    const float* cpw = nullptr; const float* cpb = nullptr;

    for (int i = 0; i < n_in; ++i) {
        const long long sz = in_sizes[i];
        const void* p = d_in[i];
        switch (sz) {
            case 67108864LL: past = (const float*)p; break;
            case 17825792LL: caw  = (const float*)p; break;
            case 16777216LL: cpw  = (const float*)p; break;
            case 4352LL:     cab  = (const float*)p; break;
            case 4096LL:     cpb  = (const float*)p; break;
            case 262144LL:
                if (!hidden) hidden = (const float*)p;   // 1st = hidden, 2nd = mask
                break;
            default: break;
        }
    }

    void* p_qkv = nullptr; void* p_attn = nullptr; void* p_part = nullptr;
    cudaGetSymbolAddress(&p_qkv,  g_qkv);
    cudaGetSymbolAddress(&p_attn, g_attn);
    cudaGetSymbolAddress(&p_part, g_part);

    cudaFuncSetAttribute(fattn_kernel,
                         cudaFuncAttributeMaxDynamicSharedMemorySize,
                         FATTN_SMEM_BYTES);

    float* out      = (float*)d_out;                    // output 0: [64, 4096]
    float* out_past = out + (size_t)BATCH * EMBED;      // output 1: [64, 4096, 256]

    gemm_tf32_kernel<3><<<dim3(NQKV / 32, SPLITK), 256>>>(hidden, caw, (float*)p_part, NQKV);  // #1 (3x)
    reduce_gemm_kernel<<<64 * NQKV / 256, 256>>>((const float*)p_part, cab, (float*)p_qkv, NQKV); // #2
    dummy_kernel<<<1, 32>>>();                                                                  // #3 (shim)
    fattn_kernel<<<dim3(NSEG, BATCH), 256, FATTN_SMEM_BYTES>>>(past, out_past);                 // #4 <- profiled
    combine_kernel<<<512, 512>>>();                                                             // #5
    gemm_tf32_kernel<1><<<dim3(EMBED / 32, SPLITK), 256>>>((const float*)p_attn, cpw, (float*)p_part, EMBED); // #6 (1x)
    reduce_gemm_kernel<<<64 * EMBED / 256, 256>>>((const float*)p_part, cpb, out, EMBED);       // #7
}